// round 1
// baseline (speedup 1.0000x reference)
#include <cuda_runtime.h>
#include <math.h>

// Problem constants
#define BATCH   2
#define S_LEN   2048
#define NH      16
#define DK      64
#define DM      1024
#define TOK     (BATCH * S_LEN)          // 4096 tokens

// Scratch (allocation-free rule: __device__ globals)
__device__ float g_Q[BATCH * NH * S_LEN * DK];   // [B,H,S,Dk]
__device__ float g_K[BATCH * NH * S_LEN * DK];
__device__ float g_V[BATCH * NH * S_LEN * DK];
__device__ float g_C[TOK * DM];                  // attention context [tok, H*Dk]

// ============================================================================
// SGEMM 128x128x8 tile, 8x8 microtile, 256 threads. C = A[4096,1024] @ B[1024,1024] + bias
// remap=true writes into [B,H,S,Dk] layout for Q/K/V.
// ============================================================================
__device__ __forceinline__ void sgemm_body(
    const float* __restrict__ A, const float* __restrict__ B,
    const float* __restrict__ bias, float* __restrict__ Cout, bool remap)
{
    __shared__ float As[8][128];
    __shared__ float Bs[8][128];
    const int Kd = DM, Nd = DM;

    int tid  = threadIdx.x;
    int brow = blockIdx.y << 7;
    int bcol = blockIdx.x << 7;

    // A: 128 rows x 8 k, one float4 per thread (transposed store)
    int a_r = tid >> 1;
    int a_c = (tid & 1) << 2;
    // B: 8 k x 128 n, one float4 per thread
    int b_r = tid >> 5;
    int b_c = (tid & 31) << 2;

    const float* Aload = A + (size_t)(brow + a_r) * Kd + a_c;
    const float* Bload = B + (size_t)b_r * Nd + bcol + b_c;

    int ty = tid >> 4;   // 0..15  -> rows ty*8
    int tx = tid & 15;   // 0..15  -> cols tx*8

    float acc[8][8];
#pragma unroll
    for (int i = 0; i < 8; i++)
#pragma unroll
        for (int j = 0; j < 8; j++) acc[i][j] = 0.f;

    for (int k0 = 0; k0 < Kd; k0 += 8) {
        float4 av = *(const float4*)(Aload + k0);
        float4 bv = *(const float4*)(Bload + (size_t)k0 * Nd);
        As[a_c + 0][a_r] = av.x;
        As[a_c + 1][a_r] = av.y;
        As[a_c + 2][a_r] = av.z;
        As[a_c + 3][a_r] = av.w;
        *(float4*)&Bs[b_r][b_c] = bv;
        __syncthreads();

#pragma unroll
        for (int kk = 0; kk < 8; kk++) {
            float ra[8], rb[8];
            *(float4*)&ra[0] = *(float4*)&As[kk][ty * 8];
            *(float4*)&ra[4] = *(float4*)&As[kk][ty * 8 + 4];
            *(float4*)&rb[0] = *(float4*)&Bs[kk][tx * 8];
            *(float4*)&rb[4] = *(float4*)&Bs[kk][tx * 8 + 4];
#pragma unroll
            for (int i = 0; i < 8; i++)
#pragma unroll
                for (int j = 0; j < 8; j++)
                    acc[i][j] = fmaf(ra[i], rb[j], acc[i][j]);
        }
        __syncthreads();
    }

    // Epilogue
    int c0 = bcol + tx * 8;
    float4 bias0 = *(const float4*)(bias + c0);
    float4 bias1 = *(const float4*)(bias + c0 + 4);
#pragma unroll
    for (int i = 0; i < 8; i++) {
        int r = brow + ty * 8 + i;
        float4 v0, v1;
        v0.x = acc[i][0] + bias0.x; v0.y = acc[i][1] + bias0.y;
        v0.z = acc[i][2] + bias0.z; v0.w = acc[i][3] + bias0.w;
        v1.x = acc[i][4] + bias1.x; v1.y = acc[i][5] + bias1.y;
        v1.z = acc[i][6] + bias1.z; v1.w = acc[i][7] + bias1.w;
        if (remap) {
            // token r -> (b, s); col c0 -> (h, d). out[((b*NH+h)*S + s)*DK + d]
            int b = r >> 11, s = r & (S_LEN - 1);
            int h = c0 >> 6, d = c0 & 63;
            size_t base = (((size_t)(b * NH + h) * S_LEN) + s) * DK + d;
            *(float4*)(Cout + base)     = v0;
            *(float4*)(Cout + base + 4) = v1;
        } else {
            *(float4*)(Cout + (size_t)r * Nd + c0)     = v0;
            *(float4*)(Cout + (size_t)r * Nd + c0 + 4) = v1;
        }
    }
}

// QKV fused: blockIdx.z selects which projection (better SM utilization: 768 blocks)
__global__ __launch_bounds__(256)
void qkv_kernel(const float* __restrict__ x,
                const float* __restrict__ Wq, const float* __restrict__ Wk,
                const float* __restrict__ Wv,
                const float* __restrict__ bq, const float* __restrict__ bk,
                const float* __restrict__ bv,
                float* __restrict__ Qo, float* __restrict__ Ko, float* __restrict__ Vo)
{
    int z = blockIdx.z;
    const float* W = (z == 0) ? Wq : (z == 1) ? Wk : Wv;
    const float* b = (z == 0) ? bq : (z == 1) ? bk : bv;
    float*       o = (z == 0) ? Qo : (z == 1) ? Ko : Vo;
    sgemm_body(x, W, b, o, true);
}

__global__ __launch_bounds__(256)
void proj_kernel(const float* __restrict__ A, const float* __restrict__ W,
                 const float* __restrict__ bias, float* __restrict__ Cout)
{
    sgemm_body(A, W, bias, Cout, false);
}

// ============================================================================
// Flash attention: one block = 64 query rows of one (b,h). 256 threads.
// Tiles of 64 keys; online softmax; fp32 throughout.
// Thread (ty,tx) owns rows ty*4..ty*4+3 and cols tx*4..tx*4+3.
// ============================================================================
#define AST 68   // padded smem stride (68 mod 32 = 4 -> conflict-free patterns)

__global__ __launch_bounds__(256)
void attn_kernel(const float* __restrict__ Q, const float* __restrict__ K,
                 const float* __restrict__ V, float* __restrict__ O)
{
    extern __shared__ float sm[];
    float* Qs  = sm;                  // [64][AST]  (row, k)
    float* KsT = sm + 64 * AST;       // [64][AST]  (k, key)  transposed
    float* Vs  = sm + 2 * 64 * AST;   // [64][AST]  (key, d)
    float* Ps  = sm + 3 * 64 * AST;   // [64][AST]  (row, key)

    int tid = threadIdx.x;
    int bh  = blockIdx.y;             // 0..31
    int q0  = blockIdx.x << 6;

    const float* Qp = Q + ((size_t)bh * S_LEN + q0) * DK;
    const float* Kp = K + (size_t)bh * S_LEN * DK;
    const float* Vp = V + (size_t)bh * S_LEN * DK;

    // Load Q tile (64x64), row-major padded
#pragma unroll
    for (int it = 0; it < 4; it++) {
        int idx = it * 256 + tid;
        int row = idx >> 4;
        int cb  = (idx & 15) << 2;
        *(float4*)&Qs[row * AST + cb] = *(const float4*)(Qp + row * 64 + cb);
    }

    int ty  = tid >> 4;
    int tx  = tid & 15;
    int ty4 = ty << 2;
    int tx4 = tx << 2;

    float m[4], l[4], o[4][4];
#pragma unroll
    for (int i = 0; i < 4; i++) {
        m[i] = -INFINITY; l[i] = 0.f;
#pragma unroll
        for (int j = 0; j < 4; j++) o[i][j] = 0.f;
    }

    const float kScale = 0.125f * 1.4426950408889634f;  // 1/sqrt(64) * log2(e)

    for (int kt = 0; kt < S_LEN; kt += 64) {
        __syncthreads();  // previous phase-C readers done with Vs/Ps

        // Load K transposed (conflict-free store map) and V row-major
#pragma unroll
        for (int it = 0; it < 4; it++) {
            int idx = it * 256 + tid;
            int key = (idx & 15) + (it << 4);
            int cb  = ((idx >> 4) & 15) << 2;
            float4 kv = *(const float4*)(Kp + (size_t)(kt + key) * 64 + cb);
            KsT[(cb + 0) * AST + key] = kv.x;
            KsT[(cb + 1) * AST + key] = kv.y;
            KsT[(cb + 2) * AST + key] = kv.z;
            KsT[(cb + 3) * AST + key] = kv.w;

            int row = idx >> 4;
            int cb2 = (idx & 15) << 2;
            *(float4*)&Vs[row * AST + cb2] =
                *(const float4*)(Vp + (size_t)(kt + row) * 64 + cb2);
        }
        __syncthreads();

        // Phase A: S = Q @ K^T (4x4 microtile)
        float s[4][4];
#pragma unroll
        for (int i = 0; i < 4; i++)
#pragma unroll
            for (int j = 0; j < 4; j++) s[i][j] = 0.f;

#pragma unroll 4
        for (int kkb = 0; kkb < 64; kkb += 4) {
            float qa[4][4];
#pragma unroll
            for (int i = 0; i < 4; i++)
                *(float4*)&qa[i][0] = *(const float4*)&Qs[(ty4 + i) * AST + kkb];
#pragma unroll
            for (int u = 0; u < 4; u++) {
                float4 rb = *(const float4*)&KsT[(kkb + u) * AST + tx4];
#pragma unroll
                for (int i = 0; i < 4; i++) {
                    float ra = qa[i][u];
                    s[i][0] = fmaf(ra, rb.x, s[i][0]);
                    s[i][1] = fmaf(ra, rb.y, s[i][1]);
                    s[i][2] = fmaf(ra, rb.z, s[i][2]);
                    s[i][3] = fmaf(ra, rb.w, s[i][3]);
                }
            }
        }

        // Phase B: online softmax (row groups = 16 lanes with same ty)
#pragma unroll
        for (int i = 0; i < 4; i++) {
#pragma unroll
            for (int j = 0; j < 4; j++) s[i][j] *= kScale;
            float tm = fmaxf(fmaxf(s[i][0], s[i][1]), fmaxf(s[i][2], s[i][3]));
#pragma unroll
            for (int off = 8; off >= 1; off >>= 1)
                tm = fmaxf(tm, __shfl_xor_sync(0xffffffffu, tm, off));
            float mn = fmaxf(m[i], tm);
            float f  = exp2f(m[i] - mn);
            m[i] = mn;
            float rs = 0.f;
#pragma unroll
            for (int j = 0; j < 4; j++) {
                float p = exp2f(s[i][j] - mn);
                s[i][j] = p;
                rs += p;
            }
#pragma unroll
            for (int off = 8; off >= 1; off >>= 1)
                rs += __shfl_xor_sync(0xffffffffu, rs, off);
            l[i] = l[i] * f + rs;
#pragma unroll
            for (int j = 0; j < 4; j++) o[i][j] *= f;
            float4 pw = make_float4(s[i][0], s[i][1], s[i][2], s[i][3]);
            *(float4*)&Ps[(ty4 + i) * AST + tx4] = pw;
        }
        __syncthreads();

        // Phase C: O += P @ V
#pragma unroll 4
        for (int jb = 0; jb < 64; jb += 4) {
            float pa[4][4];
#pragma unroll
            for (int i = 0; i < 4; i++)
                *(float4*)&pa[i][0] = *(const float4*)&Ps[(ty4 + i) * AST + jb];
#pragma unroll
            for (int u = 0; u < 4; u++) {
                float4 rv = *(const float4*)&Vs[(jb + u) * AST + tx4];
#pragma unroll
                for (int i = 0; i < 4; i++) {
                    float pv = pa[i][u];
                    o[i][0] = fmaf(pv, rv.x, o[i][0]);
                    o[i][1] = fmaf(pv, rv.y, o[i][1]);
                    o[i][2] = fmaf(pv, rv.z, o[i][2]);
                    o[i][3] = fmaf(pv, rv.w, o[i][3]);
                }
            }
        }
    }

    // Write context [tok, H*Dk]
    int b = bh >> 4, h = bh & 15;
#pragma unroll
    for (int i = 0; i < 4; i++) {
        float inv = 1.0f / l[i];
        float4 w = make_float4(o[i][0] * inv, o[i][1] * inv,
                               o[i][2] * inv, o[i][3] * inv);
        size_t row = (size_t)(b * S_LEN + q0 + ty4 + i);
        *(float4*)(O + row * DM + h * DK + tx4) = w;
    }
}

// ============================================================================
extern "C" void kernel_launch(void* const* d_in, const int* in_sizes, int n_in,
                              void* d_out, int out_size)
{
    (void)in_sizes; (void)n_in; (void)out_size;
    const float* x  = (const float*)d_in[0];
    const float* Wq = (const float*)d_in[1];
    const float* bq = (const float*)d_in[2];
    const float* Wk = (const float*)d_in[3];
    const float* bk = (const float*)d_in[4];
    const float* Wv = (const float*)d_in[5];
    const float* bv = (const float*)d_in[6];
    const float* Wo = (const float*)d_in[7];
    const float* bo = (const float*)d_in[8];
    float* out = (float*)d_out;

    float *Qd, *Kd, *Vd, *Cd;
    cudaGetSymbolAddress((void**)&Qd, g_Q);
    cudaGetSymbolAddress((void**)&Kd, g_K);
    cudaGetSymbolAddress((void**)&Vd, g_V);
    cudaGetSymbolAddress((void**)&Cd, g_C);

    static const int kAttnSmem = 4 * 64 * AST * (int)sizeof(float);  // 69632
    cudaFuncSetAttribute(attn_kernel, cudaFuncAttributeMaxDynamicSharedMemorySize,
                         kAttnSmem);

    // 1) QKV projections (fused grid, z = which)
    dim3 gGemm(DM / 128, TOK / 128, 3);
    qkv_kernel<<<gGemm, 256>>>(x, Wq, Wk, Wv, bq, bk, bv, Qd, Kd, Vd);

    // 2) Attention
    dim3 gAttn(S_LEN / 64, BATCH * NH);
    attn_kernel<<<gAttn, 256, kAttnSmem>>>(Qd, Kd, Vd, Cd);

    // 3) Output projection
    dim3 gProj(DM / 128, TOK / 128, 1);
    proj_kernel<<<gProj, 256>>>(Cd, Wo, bo, out);
}